// round 4
// baseline (speedup 1.0000x reference)
#include <cuda_runtime.h>
#include <cstdint>

// out[mu[k], e] += X1[m1[k], e] * X2[m2[k], e] * mult[k]
// M=9 channels, K~100 terms (runtime), ND = N*D = 2^20, fp32.
//
// Fused kernel, 2 float4 columns per thread (2KB apart -> conflict-free LDS):
//  - TMA stages 18 channel tiles (TILE=1024 floats each) into smem.
//  - Hidden behind TMA: rank-sort terms by (mu,m1,m2), build padded program
//    (segments padded to multiple of 2 with mult=0 dummies).
//  - Main loop: flat unroll-2 term loop; X1 operand register-cached per
//    column, reloaded via predicated ld.shared only when (mu,m1) changes;
//    packed f32x2 math; scalar overhead amortized over both columns.

#define M_CH    9
#define TILE    1024                   // floats per channel per block
#define TILE_B  (TILE * 4)             // 4096 bytes
#define HALF_B  (TILE_B / 2)           // 2048 bytes: column-pair spacing
#define THREADS 128
#define MAXK    128
#define PROGMAX 144

struct Smem {
    float4 sx[2 * M_CH * (TILE / 4)];  // 73728 B: X1 tiles then X2 tiles
    int4   prog[PROGMAX];
    int    rawkey[MAXK];
    int    skey[MAXK];
    int    smlt[MAXK];
    int    seg[M_CH + 1];
    int    pseg[M_CH + 1];
    unsigned long long mbar;
};

__global__ void __launch_bounds__(THREADS, 2)
fused_kernel(const float* __restrict__ X1, const float* __restrict__ X2,
             const int* __restrict__ m1, const int* __restrict__ m2,
             const int* __restrict__ mu, const float* __restrict__ mult,
             float* __restrict__ out, int nd4, int K)
{
    extern __shared__ char smem_raw[];
    Smem* s = (Smem*)smem_raw;
    const int t = threadIdx.x;
    const int base4 = blockIdx.x * (TILE / 4);
    const uint32_t mbar_addr = (uint32_t)__cvta_generic_to_shared(&s->mbar);

    // ---- phase 0: raw keys, mbarrier init ---------------------------------
    if (t < K)
        s->rawkey[t] = (mu[t] << 8) | (m1[t] << 4) | m2[t];
    if (t == 0) {
        asm volatile("mbarrier.init.shared.b64 [%0], %1;"
                     :: "r"(mbar_addr), "r"(1) : "memory");
        asm volatile("fence.proxy.async.shared::cta;" ::: "memory");
    }
    __syncthreads();

    // ---- phase 1: TMA issue (t0) + rank sort + mu histogram ---------------
    if (t == 0) {
        const uint32_t bytes = 2 * M_CH * TILE_B;
        asm volatile("mbarrier.arrive.expect_tx.shared.b64 _, [%0], %1;"
                     :: "r"(mbar_addr), "r"(bytes) : "memory");
        uint32_t dst = (uint32_t)__cvta_generic_to_shared(&s->sx[0]);
        const char* src1 = (const char*)(X1 + (size_t)base4 * 4);
        const char* src2 = (const char*)(X2 + (size_t)base4 * 4);
        const size_t chanstride = (size_t)nd4 * 16;
#pragma unroll
        for (int m = 0; m < M_CH; m++) {
            asm volatile(
                "cp.async.bulk.shared::cta.global.mbarrier::complete_tx::bytes "
                "[%0], [%1], %2, [%3];"
                :: "r"(dst + m * TILE_B), "l"(src1 + m * chanstride),
                   "r"((uint32_t)TILE_B), "r"(mbar_addr) : "memory");
            asm volatile(
                "cp.async.bulk.shared::cta.global.mbarrier::complete_tx::bytes "
                "[%0], [%1], %2, [%3];"
                :: "r"(dst + (M_CH + m) * TILE_B), "l"(src2 + m * chanstride),
                   "r"((uint32_t)TILE_B), "r"(mbar_addr) : "memory");
        }
    }
    if (t < K) {
        const int mykey = s->rawkey[t];
        int r = 0;
        for (int j = 0; j < K; j++) {
            int kj = s->rawkey[j];
            r += (kj < mykey) | ((kj == mykey) & (j < t));
        }
        s->skey[r] = mykey;
        s->smlt[r] = __float_as_int(mult[t]);
    }
    if (t <= M_CH) {                   // seg[m] = #{k : mu_k < m}
        int c = 0;
        for (int j = 0; j < K; j++) c += ((s->rawkey[j] >> 8) < t);
        s->seg[t] = c;
    }
    __syncthreads();

    // ---- phase 2a: padded segment starts + dummy terms --------------------
    if (t == 0) {
        int p = 0;
        for (int m = 0; m < M_CH; m++) {
            s->pseg[m] = p;
            int len  = s->seg[m + 1] - s->seg[m];
            int plen = (len + 1) & ~1;             // pad to multiple of 2
            for (int d = len; d < plen; d++)
                s->prog[p + d] = make_int4(0, 0, 0, 0);   // mult=0 dummy
            p += plen;
        }
        s->pseg[M_CH] = p;
    }
    __syncthreads();

    // ---- phase 2b: scatter real terms into padded program -----------------
    if (t < K) {
        const int key = s->skey[t];
        const int m   = key >> 8;
        const int pos = s->pseg[m] + (t - s->seg[m]);
        const int reload = (t == 0) || ((s->skey[t - 1] >> 4) != (key >> 4));
        int4 v;
        v.x = ((key >> 4) & 15) * TILE_B;                  // X1 smem offset
        v.y = M_CH * TILE_B + (key & 15) * TILE_B;         // X2 smem offset
        v.z = s->smlt[t];
        v.w = reload;
        s->prog[pos] = v;
    }
    __syncthreads();

    // ---- wait for TMA -----------------------------------------------------
    asm volatile(
        "{\n\t.reg .pred P;\n\t"
        "W_%=:\n\t"
        "mbarrier.try_wait.parity.acquire.cta.shared::cta.b64 P, [%0], 0, 0x989680;\n\t"
        "@P bra.uni D_%=;\n\t"
        "bra.uni W_%=;\n\t"
        "D_%=:\n\t}"
        :: "r"(mbar_addr) : "memory");

    // ---- main loop: 2 columns per thread ----------------------------------
    const uint32_t sx0 = (uint32_t)__cvta_generic_to_shared(&s->sx[0]);
    const uint32_t p1 = sx0 + t * 16;          // column A base
    const uint32_t p2 = p1 + HALF_B;           // column B base (+2KB)

    ulonglong2 a1, a2;
    a1.x = a1.y = a2.x = a2.y = 0ull;
    float4* __restrict__ out4 = (float4*)out;
    int kptr = 0;

#pragma unroll
    for (int m = 0; m < M_CH; m++) {
        ulonglong2 acc1, acc2;
        acc1.x = acc1.y = acc2.x = acc2.y = 0ull;
        const int k1 = s->pseg[m + 1];
        for (int k = kptr; k < k1; k += 2) {
#pragma unroll
            for (int u = 0; u < 2; u++) {
                int4 tm = s->prog[k + u];                  // broadcast LDS.128
                // predicated X1 reload for both columns
                asm("{\n\t.reg .pred p;\n\t"
                    "setp.ne.s32 p, %4, 0;\n\t"
                    "@p ld.shared.v2.u64 {%0, %1}, [%5];\n\t"
                    "@p ld.shared.v2.u64 {%2, %3}, [%6];\n\t}"
                    : "+l"(a1.x), "+l"(a1.y), "+l"(a2.x), "+l"(a2.y)
                    : "r"(tm.w), "r"(p1 + tm.x), "r"(p2 + tm.x));
                ulonglong2 b1, b2;
                asm("ld.shared.v2.u64 {%0, %1}, [%2];"
                    : "=l"(b1.x), "=l"(b1.y) : "r"(p1 + tm.y));
                asm("ld.shared.v2.u64 {%0, %1}, [%2];"
                    : "=l"(b2.x), "=l"(b2.y) : "r"(p2 + tm.y));
                unsigned long long c2;
                asm("mov.b64 %0, {%1, %1};" : "=l"(c2) : "r"(tm.z));
                asm("mul.rn.f32x2 %0, %1, %2;" : "=l"(b1.x) : "l"(c2), "l"(b1.x));
                asm("mul.rn.f32x2 %0, %1, %2;" : "=l"(b1.y) : "l"(c2), "l"(b1.y));
                asm("mul.rn.f32x2 %0, %1, %2;" : "=l"(b2.x) : "l"(c2), "l"(b2.x));
                asm("mul.rn.f32x2 %0, %1, %2;" : "=l"(b2.y) : "l"(c2), "l"(b2.y));
                asm("fma.rn.f32x2 %0, %1, %2, %3;"
                    : "=l"(acc1.x) : "l"(b1.x), "l"(a1.x), "l"(acc1.x));
                asm("fma.rn.f32x2 %0, %1, %2, %3;"
                    : "=l"(acc1.y) : "l"(b1.y), "l"(a1.y), "l"(acc1.y));
                asm("fma.rn.f32x2 %0, %1, %2, %3;"
                    : "=l"(acc2.x) : "l"(b2.x), "l"(a2.x), "l"(acc2.x));
                asm("fma.rn.f32x2 %0, %1, %2, %3;"
                    : "=l"(acc2.y) : "l"(b2.y), "l"(a2.y), "l"(acc2.y));
            }
        }
        kptr = k1;
        const size_t rowbase = (size_t)m * nd4 + base4;
        *(ulonglong2*)&out4[rowbase + t]       = acc1;     // STG.128
        *(ulonglong2*)&out4[rowbase + 128 + t] = acc2;     // STG.128
    }
}

extern "C" void kernel_launch(void* const* d_in, const int* in_sizes, int n_in,
                              void* d_out, int out_size)
{
    const float* X1   = (const float*)d_in[0];
    const float* X2   = (const float*)d_in[1];
    const int*   m1   = (const int*)d_in[2];
    const int*   m2   = (const int*)d_in[3];
    const int*   mu   = (const int*)d_in[4];
    const float* mult = (const float*)d_in[5];
    float*       out  = (float*)d_out;

    const int K   = in_sizes[2];
    const int ND  = in_sizes[0] / M_CH;    // N*D
    const int nd4 = ND / 4;

    const int smem = (int)sizeof(Smem);
    cudaFuncSetAttribute(fused_kernel,
                         cudaFuncAttributeMaxDynamicSharedMemorySize, smem);
    fused_kernel<<<ND / TILE, THREADS, smem>>>(X1, X2, m1, m2, mu, mult,
                                               out, nd4, K);
}

// round 5
// speedup vs baseline: 1.0210x; 1.0210x over previous
#include <cuda_runtime.h>
#include <cstdint>

// out[mu[k], e] += X1[m1[k], e] * X2[m2[k], e] * mult[k]
// M=9 channels, K~100 terms (runtime), ND = N*D = 2^20, fp32.
//
// Fused single kernel, 1 float4 column per thread, 5 CTAs/SM:
//  - TMA (cp.async.bulk) stages 18 channel tiles (512 floats each) into smem.
//  - Hidden behind TMA: stable rank-sort terms by mu, build program padded to
//    multiple of 4 per mu-segment; prog entry = {off1, off2, mult, mult}.
//  - Main loop: 9 mu-segments, unroll-4 flat term loop, 4 prog entries
//    batch-loaded per group; unconditional a/b LDS.128; packed f32x2 math.

#define M_CH    9
#define TILE    512                    // floats per channel per block
#define TILE_B  (TILE * 4)             // 2048 bytes
#define THREADS 128
#define MAXK    128
#define PROGMAX 136                    // K + 9*3 pads max

struct Smem {
    float4 sx[2 * M_CH * (TILE / 4)];  // 36864 B: X1 tiles then X2 tiles
    int4   prog[PROGMAX];              // 2176 B
    int    rawmu[MAXK];
    int    rnk[MAXK];
    int    seg[M_CH + 1];
    int    pseg[M_CH + 1];
    unsigned long long mbar;
};

__global__ void __launch_bounds__(THREADS, 5)
fused_kernel(const float* __restrict__ X1, const float* __restrict__ X2,
             const int* __restrict__ m1, const int* __restrict__ m2,
             const int* __restrict__ mu, const float* __restrict__ mult,
             float* __restrict__ out, int nd4, int K)
{
    __shared__ Smem s;
    const int t = threadIdx.x;
    const int base4 = blockIdx.x * (TILE / 4);
    const uint32_t mbar_addr = (uint32_t)__cvta_generic_to_shared(&s.mbar);

    // ---- phase 0: mu keys to smem, mbarrier init --------------------------
    if (t < K) s.rawmu[t] = mu[t];
    if (t == 0) {
        asm volatile("mbarrier.init.shared.b64 [%0], %1;"
                     :: "r"(mbar_addr), "r"(1) : "memory");
        asm volatile("fence.proxy.async.shared::cta;" ::: "memory");
    }
    __syncthreads();

    // ---- phase 1: TMA issue (t0); stable rank by mu; mu histogram ---------
    if (t == 0) {
        const uint32_t bytes = 2 * M_CH * TILE_B;
        asm volatile("mbarrier.arrive.expect_tx.shared.b64 _, [%0], %1;"
                     :: "r"(mbar_addr), "r"(bytes) : "memory");
        uint32_t dst = (uint32_t)__cvta_generic_to_shared(&s.sx[0]);
        const char* src1 = (const char*)(X1 + (size_t)base4 * 4);
        const char* src2 = (const char*)(X2 + (size_t)base4 * 4);
        const size_t chanstride = (size_t)nd4 * 16;
#pragma unroll
        for (int m = 0; m < M_CH; m++) {
            asm volatile(
                "cp.async.bulk.shared::cta.global.mbarrier::complete_tx::bytes "
                "[%0], [%1], %2, [%3];"
                :: "r"(dst + m * TILE_B), "l"(src1 + m * chanstride),
                   "r"((uint32_t)TILE_B), "r"(mbar_addr) : "memory");
            asm volatile(
                "cp.async.bulk.shared::cta.global.mbarrier::complete_tx::bytes "
                "[%0], [%1], %2, [%3];"
                :: "r"(dst + (M_CH + m) * TILE_B), "l"(src2 + m * chanstride),
                   "r"((uint32_t)TILE_B), "r"(mbar_addr) : "memory");
        }
    }
    if (t < K) {
        const int mymu = s.rawmu[t];
        int r = 0;
        for (int j = 0; j < K; j++) {
            int mj = s.rawmu[j];
            r += (mj < mymu) | ((mj == mymu) & (j < t));
        }
        s.rnk[t] = r;
    }
    if (t <= M_CH) {                   // seg[m] = #{k : mu_k < m}
        int c = 0;
        for (int j = 0; j < K; j++) c += (s.rawmu[j] < t);
        s.seg[t] = c;
    }
    __syncthreads();

    // ---- phase 2a: padded segment starts + inert pad terms (t0) -----------
    if (t == 0) {
        int p = 0;
        for (int m = 0; m < M_CH; m++) {
            s.pseg[m] = p;
            int len  = s.seg[m + 1] - s.seg[m];
            int plen = (len + 3) & ~3;                  // pad to multiple of 4
            for (int d = len; d < plen; d++)
                s.prog[p + d] = make_int4(0, M_CH * TILE_B, 0, 0);  // mult=0
            p += plen;
        }
        s.pseg[M_CH] = p;
    }
    __syncthreads();

    // ---- phase 2b: scatter real terms -------------------------------------
    if (t < K) {
        const int m   = s.rawmu[t];
        const int pos = s.pseg[m] + (s.rnk[t] - s.seg[m]);
        const int mb  = __float_as_int(mult[t]);
        int4 v;
        v.x = m1[t] * TILE_B;                          // X1 smem offset
        v.y = M_CH * TILE_B + m2[t] * TILE_B;          // X2 smem offset
        v.z = mb;                                      // mult (lo)
        v.w = mb;                                      // mult (hi) -> free pack
        s.prog[pos] = v;
    }
    __syncthreads();

    // ---- wait for TMA -----------------------------------------------------
    asm volatile(
        "{\n\t.reg .pred P;\n\t"
        "W_%=:\n\t"
        "mbarrier.try_wait.parity.acquire.cta.shared::cta.b64 P, [%0], 0, 0x989680;\n\t"
        "@P bra.uni D_%=;\n\t"
        "bra.uni W_%=;\n\t"
        "D_%=:\n\t}"
        :: "r"(mbar_addr) : "memory");

    // ---- main loop --------------------------------------------------------
    const uint32_t sx0 = (uint32_t)__cvta_generic_to_shared(&s.sx[0]);
    const uint32_t p1  = sx0 + t * 16;                 // this thread's column
    float4* __restrict__ out4 = (float4*)out;
    int kptr = 0;

#pragma unroll
    for (int m = 0; m < M_CH; m++) {
        ulonglong2 acc; acc.x = acc.y = 0ull;
        const int k1 = s.pseg[m + 1];
        for (int k = kptr; k < k1; k += 4) {
            // batch-load 4 prog entries -> 4 independent LDS chains
            int4 tm0 = s.prog[k + 0];
            int4 tm1 = s.prog[k + 1];
            int4 tm2 = s.prog[k + 2];
            int4 tm3 = s.prog[k + 3];
#pragma unroll
            for (int u = 0; u < 4; u++) {
                int4 tm = (u == 0) ? tm0 : (u == 1) ? tm1 : (u == 2) ? tm2 : tm3;
                ulonglong2 a, b;
                asm("ld.shared.v2.u64 {%0, %1}, [%2];"
                    : "=l"(a.x), "=l"(a.y) : "r"(p1 + tm.x));
                asm("ld.shared.v2.u64 {%0, %1}, [%2];"
                    : "=l"(b.x), "=l"(b.y) : "r"(p1 + tm.y));
                unsigned long long c2;
                asm("mov.b64 %0, {%1, %2};" : "=l"(c2) : "r"(tm.z), "r"(tm.w));
                asm("mul.rn.f32x2 %0, %1, %2;" : "=l"(b.x) : "l"(c2), "l"(b.x));
                asm("mul.rn.f32x2 %0, %1, %2;" : "=l"(b.y) : "l"(c2), "l"(b.y));
                asm("fma.rn.f32x2 %0, %1, %2, %3;"
                    : "=l"(acc.x) : "l"(b.x), "l"(a.x), "l"(acc.x));
                asm("fma.rn.f32x2 %0, %1, %2, %3;"
                    : "=l"(acc.y) : "l"(b.y), "l"(a.y), "l"(acc.y));
            }
        }
        kptr = k1;
        *(ulonglong2*)&out4[(size_t)m * nd4 + base4 + t] = acc;   // STG.128
    }
}

extern "C" void kernel_launch(void* const* d_in, const int* in_sizes, int n_in,
                              void* d_out, int out_size)
{
    const float* X1   = (const float*)d_in[0];
    const float* X2   = (const float*)d_in[1];
    const int*   m1   = (const int*)d_in[2];
    const int*   m2   = (const int*)d_in[3];
    const int*   mu   = (const int*)d_in[4];
    const float* mult = (const float*)d_in[5];
    float*       out  = (float*)d_out;

    const int K   = in_sizes[2];
    const int ND  = in_sizes[0] / M_CH;    // N*D
    const int nd4 = ND / 4;

    fused_kernel<<<ND / TILE, THREADS>>>(X1, X2, m1, m2, mu, mult, out, nd4, K);
}